// round 12
// baseline (speedup 1.0000x reference)
#include <cuda_runtime.h>
#include <cuda_bf16.h>
#include <math.h>

#define HS_B     8192
#define HS_P     32
#define HS_D     128
#define HS_GRID  888                // 148 SMs x 6 CTAs (best measured config)
#define HS_ITEMS (HS_B * 4)         // (row, 8-pos chunk) work items
#define FULLMASK 0xffffffffu

// Per-CTA {loss_sum, count} partials + completion counter (zero-init).
__device__ float2       g_hs_partial[HS_GRID];
__device__ unsigned int g_hs_ctr;

// ---------------------------------------------------------------------------
// Balanced persistent kernel (R7 structure). Item = (b, c): positions
// [8c, 8c+8) of row b. Lanes 0..7 carry the item's indices/codes (one
// coalesced 32-B load each + SHFL broadcast). Row reads are split into
// 4 x LDG.32 per row (lane reads elements lane, lane+32, lane+64, lane+96):
// every LDG touches exactly one 128-B line, so L1tex wavefronts are priced
// at the 1.0 cyc/wf cross-LDG rate instead of 2.07 cyc/wf within-LDG
// replays. The folding merge network leaves the complete dot for position
// k in lane group k = lane>>2 (warp sum is mapping-invariant).
// ---------------------------------------------------------------------------
__global__ __launch_bounds__(256, 6)
void hs_fused_kernel(const float* __restrict__ hidden,
                     const int*   __restrict__ target_path,
                     const int*   __restrict__ target_path_len,
                     const int*   __restrict__ target_code,
                     const float* __restrict__ embed_table,
                     float*       __restrict__ out) {
    const int tid  = threadIdx.x;
    const int warp = tid >> 5;
    const int lane = tid & 31;
    const int gw   = blockIdx.x * 8 + warp;
    const int GW   = gridDim.x * 8;

    const int  j     = lane >> 2;           // value index this lane finalizes
    const bool canon = (lane & 3) == 0;     // one canonical lane per value

    float accL = 0.0f;                      // loss accumulator
    float accC = 0.0f;                      // count accumulator (lane 0)

    for (int item = gw; item < HS_ITEMS; item += GW) {
        const int b    = item >> 2;
        const int base = (item & 3) * 8;
        const int L    = __ldg(&target_path_len[b]);
        if (base >= L) continue;            // warp-uniform skip
        const int n = min(8, L - base);

        // Lanes 0..7 fetch this chunk's indices and codes (coalesced).
        int idx_l = 0, code_l = 0;
        if (lane < 8) {
            idx_l  = target_path[b * HS_P + base + lane];
            code_l = target_code[b * HS_P + base + lane];
        }
        const unsigned codemask =
            __ballot_sync(FULLMASK, (lane < 8) && (code_l != 0));

        // Hidden row, strided mapping: elements lane, +32, +64, +96.
        // Each LDG.32 covers exactly one 128-B line.
        const float* hrow = hidden + (size_t)b * HS_D;
        const float h0 = __ldg(&hrow[lane]);
        const float h1 = __ldg(&hrow[lane + 32]);
        const float h2 = __ldg(&hrow[lane + 64]);
        const float h3 = __ldg(&hrow[lane + 96]);

        // Up to 8 independent embed-row gathers, 4 x LDG.32 each.
        float d[8];
        #pragma unroll
        for (int i = 0; i < 8; i++) {
            const int node = __shfl_sync(FULLMASK, idx_l, i);
            d[i] = 0.0f;
            if (i < n) {
                const float* er = embed_table + (size_t)node * HS_D;
                const float e0 = __ldg(&er[lane]);
                const float e1 = __ldg(&er[lane + 32]);
                const float e2 = __ldg(&er[lane + 64]);
                const float e3 = __ldg(&er[lane + 96]);
                d[i] = fmaf(e0, h0, fmaf(e1, h1, fmaf(e2, h2, e3 * h3)));
            }
        }

        // Folding merge network: 8 values -> 1 per 4-lane group.
        float e4[4];
        #pragma unroll
        for (int i = 0; i < 4; i++) {
            const float send = (lane & 16) ? d[i]     : d[i + 4];
            const float keep = (lane & 16) ? d[i + 4] : d[i];
            e4[i] = keep + __shfl_xor_sync(FULLMASK, send, 16);
        }
        float f2[2];
        #pragma unroll
        for (int i = 0; i < 2; i++) {
            const float send = (lane & 8) ? e4[i]     : e4[i + 2];
            const float keep = (lane & 8) ? e4[i + 2] : e4[i];
            f2[i] = keep + __shfl_xor_sync(FULLMASK, send, 8);
        }
        {
            const float send = (lane & 4) ? f2[0] : f2[1];
            const float keep = (lane & 4) ? f2[1] : f2[0];
            f2[0] = keep + __shfl_xor_sync(FULLMASK, send, 4);
        }
        float g = f2[0];
        g += __shfl_xor_sync(FULLMASK, g, 2);
        g += __shfl_xor_sync(FULLMASK, g, 1);
        // Lane group k = lane>>2 holds the complete dot for position k.

        if (canon && j < n) {
            const float x = ((codemask >> j) & 1u) ? g : -g;
            accL += __logf(1.0f + __expf(-x));   // -log(sigmoid(x))
        }
        if (lane == 0) accC += (float)n;
    }

    // Warp-level reduce of per-lane accumulators (once, after the loop).
    #pragma unroll
    for (int off = 16; off > 0; off >>= 1) {
        accL += __shfl_xor_sync(FULLMASK, accL, off);
        accC += __shfl_xor_sync(FULLMASK, accC, off);
    }

    __shared__ float2 swsum[8];
    if (lane == 0) swsum[warp] = make_float2(accL, accC);
    __syncthreads();

    __shared__ bool is_last;
    if (tid == 0) {
        float2 t = make_float2(0.0f, 0.0f);
        #pragma unroll
        for (int i = 0; i < 8; i++) { t.x += swsum[i].x; t.y += swsum[i].y; }
        g_hs_partial[blockIdx.x] = t;
        __threadfence();
        const unsigned prev = atomicAdd(&g_hs_ctr, 1u);
        is_last = (prev == (unsigned)(gridDim.x - 1));
    }
    __syncthreads();

    // Last CTA reduces the partials in fixed order and writes the scalar.
    if (is_last) {
        float ls = 0.0f, cs = 0.0f;
        #pragma unroll
        for (int i = 0; i < 4; i++) {
            const int k = tid + i * 256;
            if (k < HS_GRID) {
                const float2 v = __ldcg(&g_hs_partial[k]);
                ls += v.x;
                cs += v.y;
            }
        }
        #pragma unroll
        for (int off = 16; off > 0; off >>= 1) {
            ls += __shfl_xor_sync(FULLMASK, ls, off);
            cs += __shfl_xor_sync(FULLMASK, cs, off);
        }
        __shared__ float sl[8], sc[8];
        if (lane == 0) { sl[warp] = ls; sc[warp] = cs; }
        __syncthreads();
        if (tid == 0) {
            float tl = 0.0f, tc = 0.0f;
            #pragma unroll
            for (int i = 0; i < 8; i++) { tl += sl[i]; tc += sc[i]; }
            out[0] = (float)((double)tl / (double)tc);
            g_hs_ctr = 0;   // reset for next graph replay
        }
    }
}

// ---------------------------------------------------------------------------
// Inputs (metadata order): hidden_ f32[B,D], target i32[B] (unused),
// target_path i32[B,P], target_path_len i32[B], target_code i32[B,P],
// embed_table f32[V,D].  Output: f32 scalar.
// ---------------------------------------------------------------------------
extern "C" void kernel_launch(void* const* d_in, const int* in_sizes, int n_in,
                              void* d_out, int out_size) {
    const float* hidden      = (const float*)d_in[0];
    const int*   target_path = (const int*)  d_in[2];
    const int*   path_len    = (const int*)  d_in[3];
    const int*   target_code = (const int*)  d_in[4];
    const float* embed_table = (const float*)d_in[5];
    float*       out         = (float*)d_out;

    hs_fused_kernel<<<HS_GRID, 256>>>(hidden, target_path, path_len,
                                      target_code, embed_table, out);
}

// round 13
// speedup vs baseline: 1.1373x; 1.1373x over previous
#include <cuda_runtime.h>
#include <cuda_bf16.h>
#include <math.h>

#define HS_B     8192
#define HS_P     32
#define HS_D     128
#define HS_GRID  740                // 148 SMs x 5 CTAs
#define HS_ITEMS (HS_B * 2)         // (row, 16-pos half) work items
#define FULLMASK 0xffffffffu

// Per-CTA {loss_sum, count} partials + completion counter (zero-init).
__device__ float2       g_hs_partial[HS_GRID];
__device__ unsigned int g_hs_ctr;

// ---------------------------------------------------------------------------
// Balanced persistent kernel, 16-position items. Item = (b, h): positions
// [16h, 16h+16) of row b. Lanes 0..15 carry the item's indices/codes (one
// coalesced load each + SHFL broadcast). 16 independent float4 row-gathers
// per item (16-deep MLP per stall window). Folding merge network (offsets
// 16/8/4/2 + final butterfly = 16 SHFL) leaves the complete dot for position
// k in 2-lane group k = lane>>1; the even lane of each group computes the
// softplus. One hidden-row load and one control load per 16 positions.
// ---------------------------------------------------------------------------
__global__ __launch_bounds__(256, 5)
void hs_fused_kernel(const float* __restrict__ hidden,
                     const int*   __restrict__ target_path,
                     const int*   __restrict__ target_path_len,
                     const int*   __restrict__ target_code,
                     const float* __restrict__ embed_table,
                     float*       __restrict__ out) {
    const int tid  = threadIdx.x;
    const int warp = tid >> 5;
    const int lane = tid & 31;
    const int gw   = blockIdx.x * 8 + warp;
    const int GW   = gridDim.x * 8;

    const int  j     = lane >> 1;           // position this 2-lane group owns
    const bool canon = (lane & 1) == 0;     // one canonical lane per position

    float accL = 0.0f;                      // loss accumulator
    float accC = 0.0f;                      // count accumulator (lane 0)

    for (int item = gw; item < HS_ITEMS; item += GW) {
        const int b    = item >> 1;
        const int base = (item & 1) * 16;
        const int L    = __ldg(&target_path_len[b]);
        if (base >= L) continue;            // warp-uniform skip
        const int n = min(16, L - base);

        // Lanes 0..15 fetch this chunk's indices and codes (coalesced).
        int idx_l = 0, code_l = 0;
        if (lane < 16) {
            idx_l  = target_path[b * HS_P + base + lane];
            code_l = target_code[b * HS_P + base + lane];
        }
        const unsigned codemask =
            __ballot_sync(FULLMASK, (lane < 16) && (code_l != 0));

        // Hidden row: one float4 per lane (512 B, L2-resident).
        const float4 hv =
            reinterpret_cast<const float4*>(hidden + (size_t)b * HS_D)[lane];

        // Up to 16 independent embed-row gathers in flight.
        float d[16];
        #pragma unroll
        for (int i = 0; i < 16; i++) {
            const int node = __shfl_sync(FULLMASK, idx_l, i);
            d[i] = 0.0f;
            if (i < n) {
                const float4 e = reinterpret_cast<const float4*>(
                    embed_table + (size_t)node * HS_D)[lane];
                d[i] = fmaf(e.x, hv.x, fmaf(e.y, hv.y,
                            fmaf(e.z, hv.z, e.w * hv.w)));
            }
        }

        // Folding merge network: 16 values -> 1 per 2-lane group.
        // After folds with offsets {16,8,4,2}, lane bit {4,3,2,1} selects
        // value-index bit {3,2,1,0}; final butterfly (offset 1) completes
        // the 32-lane sum. Group k = lane>>1 ends with position k's dot.
        float e8[8];
        #pragma unroll
        for (int i = 0; i < 8; i++) {
            const float send = (lane & 16) ? d[i]     : d[i + 8];
            const float keep = (lane & 16) ? d[i + 8] : d[i];
            e8[i] = keep + __shfl_xor_sync(FULLMASK, send, 16);
        }
        float e4[4];
        #pragma unroll
        for (int i = 0; i < 4; i++) {
            const float send = (lane & 8) ? e8[i]     : e8[i + 4];
            const float keep = (lane & 8) ? e8[i + 4] : e8[i];
            e4[i] = keep + __shfl_xor_sync(FULLMASK, send, 8);
        }
        float f2[2];
        #pragma unroll
        for (int i = 0; i < 2; i++) {
            const float send = (lane & 4) ? e4[i]     : e4[i + 2];
            const float keep = (lane & 4) ? e4[i + 2] : e4[i];
            f2[i] = keep + __shfl_xor_sync(FULLMASK, send, 4);
        }
        float g;
        {
            const float send = (lane & 2) ? f2[0] : f2[1];
            const float keep = (lane & 2) ? f2[1] : f2[0];
            g = keep + __shfl_xor_sync(FULLMASK, send, 2);
        }
        g += __shfl_xor_sync(FULLMASK, g, 1);
        // 2-lane group k = lane>>1 holds the complete dot for position k.

        if (canon && j < n) {
            const float x = ((codemask >> j) & 1u) ? g : -g;
            accL += __logf(1.0f + __expf(-x));   // -log(sigmoid(x))
        }
        if (lane == 0) accC += (float)n;
    }

    // Warp-level reduce of per-lane accumulators (once, after the loop).
    #pragma unroll
    for (int off = 16; off > 0; off >>= 1) {
        accL += __shfl_xor_sync(FULLMASK, accL, off);
        accC += __shfl_xor_sync(FULLMASK, accC, off);
    }

    __shared__ float2 swsum[8];
    if (lane == 0) swsum[warp] = make_float2(accL, accC);
    __syncthreads();

    __shared__ bool is_last;
    if (tid == 0) {
        float2 t = make_float2(0.0f, 0.0f);
        #pragma unroll
        for (int i = 0; i < 8; i++) { t.x += swsum[i].x; t.y += swsum[i].y; }
        g_hs_partial[blockIdx.x] = t;
        __threadfence();
        const unsigned prev = atomicAdd(&g_hs_ctr, 1u);
        is_last = (prev == (unsigned)(gridDim.x - 1));
    }
    __syncthreads();

    // Last CTA reduces the partials in fixed order and writes the scalar.
    if (is_last) {
        float ls = 0.0f, cs = 0.0f;
        #pragma unroll
        for (int i = 0; i < 3; i++) {
            const int k = tid + i * 256;
            if (k < HS_GRID) {
                const float2 v = __ldcg(&g_hs_partial[k]);
                ls += v.x;
                cs += v.y;
            }
        }
        #pragma unroll
        for (int off = 16; off > 0; off >>= 1) {
            ls += __shfl_xor_sync(FULLMASK, ls, off);
            cs += __shfl_xor_sync(FULLMASK, cs, off);
        }
        __shared__ float sl[8], sc[8];
        if (lane == 0) { sl[warp] = ls; sc[warp] = cs; }
        __syncthreads();
        if (tid == 0) {
            float tl = 0.0f, tc = 0.0f;
            #pragma unroll
            for (int i = 0; i < 8; i++) { tl += sl[i]; tc += sc[i]; }
            out[0] = (float)((double)tl / (double)tc);
            g_hs_ctr = 0;   // reset for next graph replay
        }
    }
}

// ---------------------------------------------------------------------------
// Inputs (metadata order): hidden_ f32[B,D], target i32[B] (unused),
// target_path i32[B,P], target_path_len i32[B], target_code i32[B,P],
// embed_table f32[V,D].  Output: f32 scalar.
// ---------------------------------------------------------------------------
extern "C" void kernel_launch(void* const* d_in, const int* in_sizes, int n_in,
                              void* d_out, int out_size) {
    const float* hidden      = (const float*)d_in[0];
    const int*   target_path = (const int*)  d_in[2];
    const int*   path_len    = (const int*)  d_in[3];
    const int*   target_code = (const int*)  d_in[4];
    const float* embed_table = (const float*)d_in[5];
    float*       out         = (float*)d_out;

    hs_fused_kernel<<<HS_GRID, 256>>>(hidden, target_path, path_len,
                                      target_code, embed_table, out);
}